// round 3
// baseline (speedup 1.0000x reference)
#include <cuda_runtime.h>

#define U_N 100000
#define I_N 50000
#define D_N 64
#define E_N 2000000
#define NN  (U_N + I_N)   // 150000

#define SCAN_ELEMS  1024
#define SCAN_BLOCKS ((NN + SCAN_ELEMS - 1) / SCAN_ELEMS)   // 147

// Scratch (allocation-free rule: __device__ globals)
__device__ __align__(256) float g_a[NN * D_N];        // 38.4 MB  (x ping)
__device__ __align__(256) float g_b[NN * D_N];        // 38.4 MB  (x pong)
__device__ __align__(256) int2  g_entries[2 * E_N];   // 32 MB CSR: {src, w-bits}
__device__ __align__(256) float g_deg[NN];
__device__ __align__(256) float g_dinv[NN];
__device__ __align__(256) int   g_cnt[NN];
__device__ __align__(256) int   g_rowstart[NN + 1];
__device__ __align__(256) int   g_cursor[NN];
__device__ __align__(256) int   g_totals[SCAN_BLOCKS];

__device__ __forceinline__ float warp_sum(float s) {
#pragma unroll
    for (int o = 16; o; o >>= 1) s += __shfl_xor_sync(0xffffffffu, s, o);
    return s;
}

// ---------------- Prologue: L0 embeddings ----------------

__global__ void user_kernel(const float* __restrict__ uw,
                            float* __restrict__ x, float* __restrict__ acc) {
    int w    = (blockIdx.x * blockDim.x + threadIdx.x) >> 5;
    int lane = threadIdx.x & 31;
    if (w >= U_N) return;
    float2 v = ((const float2*)uw)[w * 32 + lane];
    float s  = warp_sum(v.x * v.x + v.y * v.y);
    float r  = 1.0f / fmaxf(sqrtf(s), 1e-12f);
    float2 o = make_float2(v.x * r, v.y * r);
    ((float2*)x)[w * 32 + lane]   = o;
    ((float2*)acc)[w * 32 + lane] = o;
}

__global__ void item_kernel(const float* __restrict__ audio,
                            const float* __restrict__ art,
                            const float* __restrict__ alb,
                            const float* __restrict__ W,     // [64, 128]
                            const float* __restrict__ bias,  // [64]
                            const int* __restrict__ aid,
                            const int* __restrict__ bid,
                            float* __restrict__ x, float* __restrict__ acc) {
    __shared__ float WT[128 * 64];   // WT[k*64+d] = W[d*128+k]
    __shared__ float feat[8][128];
    int tid = threadIdx.x;
    for (int idx = tid; idx < 64 * 128; idx += 256) {
        int d = idx >> 7, k = idx & 127;
        WT[k * 64 + d] = W[idx];
    }
    __syncthreads();

    int w = tid >> 5, lane = tid & 31;
    int item = blockIdx.x * 8 + w;
    if (item < I_N) {
        int a = aid[item], bb = bid[item];
        feat[w][lane]      = audio[item * 64 + lane];
        feat[w][lane + 32] = audio[item * 64 + lane + 32];
        feat[w][64 + lane] = art[a * 64 + lane]      + alb[bb * 64 + lane];
        feat[w][96 + lane] = art[a * 64 + lane + 32] + alb[bb * 64 + lane + 32];
    }
    __syncwarp();
    if (item >= I_N) return;

    float a0 = 0.f, a1 = 0.f;
#pragma unroll
    for (int k = 0; k < 128; k++) {
        float f = feat[w][k];
        a0 = fmaf(f, WT[k * 64 + lane],      a0);
        a1 = fmaf(f, WT[k * 64 + lane + 32], a1);
    }
    a0 += bias[lane];
    a1 += bias[lane + 32];
    float s = warp_sum(a0 * a0 + a1 * a1);
    float r = 1.0f / fmaxf(sqrtf(s), 1e-12f);
    int base = (U_N + item) * 64;
    x[base + lane]        = a0 * r;
    x[base + lane + 32]   = a1 * r;
    acc[base + lane]      = a0 * r;
    acc[base + lane + 32] = a1 * r;
}

// ---------------- Degrees + CSR build ----------------

__global__ void node_init_kernel() {
    int n = blockIdx.x * blockDim.x + threadIdx.x;
    if (n < NN) { g_deg[n] = 1.0f; g_cnt[n] = 0; }   // self loop weight 1
}

__global__ void deg_cnt_kernel(const float* __restrict__ ew,
                               const int* __restrict__ ui,
                               const int* __restrict__ ii) {
    int e = blockIdx.x * blockDim.x + threadIdx.x;
    if (e >= E_N) return;
    float w = fmaxf(ew[e], 1e-6f);
    int u = ui[e], it = U_N + ii[e];
    atomicAdd(&g_deg[u], w);
    atomicAdd(&g_deg[it], w);
    atomicAdd(&g_cnt[u], 1);
    atomicAdd(&g_cnt[it], 1);
}

__global__ void dinv_kernel() {
    int n = blockIdx.x * blockDim.x + threadIdx.x;
    if (n < NN) g_dinv[n] = rsqrtf(g_deg[n]);
}

// --- scan A: per-block (1024-elem) totals ---
__global__ void scanA_kernel() {
    int t = threadIdx.x;
    int base = blockIdx.x * SCAN_ELEMS + t * 4;
    int s = 0;
#pragma unroll
    for (int k = 0; k < 4; k++) {
        int id = base + k;
        if (id < NN) s += g_cnt[id];
    }
    __shared__ int sh[256];
    sh[t] = s; __syncthreads();
    for (int o = 128; o; o >>= 1) {
        if (t < o) sh[t] += sh[t + o];
        __syncthreads();
    }
    if (t == 0) g_totals[blockIdx.x] = sh[0];
}

// --- scan B: exclusive scan of block totals (single block) ---
__global__ void scanB_kernel() {
    __shared__ int sh[256];
    int t = threadIdx.x;
    int mine = (t < SCAN_BLOCKS) ? g_totals[t] : 0;
    sh[t] = mine; __syncthreads();
    for (int o = 1; o < 256; o <<= 1) {
        int v = (t >= o) ? sh[t - o] : 0;
        __syncthreads();
        sh[t] += v;
        __syncthreads();
    }
    if (t < SCAN_BLOCKS) g_totals[t] = sh[t] - mine;  // exclusive
    if (t == 255) g_rowstart[NN] = sh[255];           // grand total = 2E
}

// --- scan C: full exclusive positions -> rowstart + cursor ---
__global__ void scanC_kernel() {
    int t = threadIdx.x;
    int base = blockIdx.x * SCAN_ELEMS + t * 4;
    int v[4]; int s = 0;
#pragma unroll
    for (int k = 0; k < 4; k++) {
        int id = base + k;
        v[k] = (id < NN) ? g_cnt[id] : 0;
        s += v[k];
    }
    __shared__ int sh[256];
    sh[t] = s; __syncthreads();
    for (int o = 1; o < 256; o <<= 1) {
        int x = (t >= o) ? sh[t - o] : 0;
        __syncthreads();
        sh[t] += x;
        __syncthreads();
    }
    int p = g_totals[blockIdx.x] + (sh[t] - s);
#pragma unroll
    for (int k = 0; k < 4; k++) {
        int id = base + k;
        if (id < NN) { g_rowstart[id] = p; g_cursor[id] = p; }
        p += v[k];
    }
}

// --- fill: scatter each edge into both endpoints' adjacency lists ---
__global__ void fill_kernel(const float* __restrict__ ew,
                            const int* __restrict__ ui,
                            const int* __restrict__ ii) {
    int e = blockIdx.x * blockDim.x + threadIdx.x;
    if (e >= E_N) return;
    int u = ui[e], it = U_N + ii[e];
    float w = fmaxf(ew[e], 1e-6f);
    float c = g_dinv[u] * w * g_dinv[it];
    int cb = __float_as_int(c);
    int pu = atomicAdd(&g_cursor[u], 1);
    int pi = atomicAdd(&g_cursor[it], 1);
    g_entries[pu] = make_int2(it, cb);
    g_entries[pi] = make_int2(u, cb);
}

// ---------------- Propagation: gather (one warp per dst row) ----------------
// xn[row] = dinv[row]^2 * x[row] + sum_{(src,c) in adj(row)} c * x[src]
// acc[row] += xn[row]
__global__ void gather_kernel(const float* __restrict__ x,
                              float* __restrict__ xn,
                              float* __restrict__ acc) {
    int row  = (blockIdx.x * blockDim.x + threadIdx.x) >> 5;
    int lane = threadIdx.x & 31;
    if (row >= NN) return;
    int s   = g_rowstart[row];
    int end = g_rowstart[row + 1];
    float di = g_dinv[row];
    float c0 = di * di;
    float2 xv = ((const float2*)x)[row * 32 + lane];
    float a0 = c0 * xv.x, a1 = c0 * xv.y;
#pragma unroll 4
    for (int p = s; p < end; p++) {
        int2 ent = __ldg(g_entries + p);           // uniform broadcast load
        float w = __int_as_float(ent.y);
        float2 v = ((const float2*)x)[ent.x * 32 + lane];
        a0 = fmaf(w, v.x, a0);
        a1 = fmaf(w, v.y, a1);
    }
    ((float2*)xn)[row * 32 + lane] = make_float2(a0, a1);
    float2 av = ((float2*)acc)[row * 32 + lane];
    ((float2*)acc)[row * 32 + lane] = make_float2(av.x + a0, av.y + a1);
}

// ---------------- Epilogue: out = l2norm(acc / 4), in place ----------------
__global__ void final_kernel(float* __restrict__ acc) {
    int w    = (blockIdx.x * blockDim.x + threadIdx.x) >> 5;
    int lane = threadIdx.x & 31;
    if (w >= NN) return;
    float2 va = ((const float2*)acc)[w * 32 + lane];
    float x0 = va.x * 0.25f;
    float x1 = va.y * 0.25f;
    float s  = warp_sum(x0 * x0 + x1 * x1);
    float r  = 1.0f / fmaxf(sqrtf(s), 1e-12f);
    ((float2*)acc)[w * 32 + lane] = make_float2(x0 * r, x1 * r);
}

// ---------------- Launch ----------------

extern "C" void kernel_launch(void* const* d_in, const int* in_sizes, int n_in,
                              void* d_out, int out_size) {
    const float* user_w      = (const float*)d_in[0];
    const float* item_audio  = (const float*)d_in[1];
    const float* artist_w    = (const float*)d_in[2];
    const float* album_w     = (const float*)d_in[3];
    const float* proj_W      = (const float*)d_in[4];
    const float* proj_b      = (const float*)d_in[5];
    const float* edge_weight = (const float*)d_in[6];
    const int*   u_idx       = (const int*)d_in[7];
    const int*   i_idx       = (const int*)d_in[8];
    const int*   artist_ids  = (const int*)d_in[9];
    const int*   album_ids   = (const int*)d_in[10];
    float* acc = (float*)d_out;

    float *pa, *pb;
    cudaGetSymbolAddress((void**)&pa, g_a);
    cudaGetSymbolAddress((void**)&pb, g_b);

    const int T = 256;
    const int node_blocks = (NN + T - 1) / T;
    const int edge_blocks = (E_N + T - 1) / T;
    const int row_blocks  = (NN * 32 + T - 1) / T;   // one warp per row

    // L0 embeddings -> x (a) and acc
    user_kernel<<<(U_N * 32) / T, T>>>(user_w, pa, acc);
    item_kernel<<<I_N / 8, T>>>(item_audio, artist_w, album_w, proj_W, proj_b,
                                artist_ids, album_ids, pa, acc);

    // Degrees, dinv, CSR build
    node_init_kernel<<<node_blocks, T>>>();
    deg_cnt_kernel<<<edge_blocks, T>>>(edge_weight, u_idx, i_idx);
    dinv_kernel<<<node_blocks, T>>>();
    scanA_kernel<<<SCAN_BLOCKS, 256>>>();
    scanB_kernel<<<1, 256>>>();
    scanC_kernel<<<SCAN_BLOCKS, 256>>>();
    fill_kernel<<<edge_blocks, T>>>(edge_weight, u_idx, i_idx);

    // 3 LGConv layers (gather, acc folded in)
    gather_kernel<<<row_blocks, T>>>(pa, pb, acc);   // x1
    gather_kernel<<<row_blocks, T>>>(pb, pa, acc);   // x2
    gather_kernel<<<row_blocks, T>>>(pa, pb, acc);   // x3

    final_kernel<<<row_blocks, T>>>(acc);
}

// round 4
// speedup vs baseline: 1.6065x; 1.6065x over previous
#include <cuda_runtime.h>

#define U_N 100000
#define I_N 50000
#define D_N 64
#define E_N 2000000
#define NN  (U_N + I_N)   // 150000

#define SCAN_ELEMS  1024
#define SCAN_BLOCKS ((NN + SCAN_ELEMS - 1) / SCAN_ELEMS)   // 147

// Scratch (allocation-free rule: __device__ globals)
__device__ __align__(256) float g_a[NN * D_N];        // x0
__device__ __align__(256) float g_b[NN * D_N];        // x1
__device__ __align__(256) float g_c[NN * D_N];        // x2
__device__ __align__(256) int2  g_entries[2 * E_N];   // CSR: {src, coef-bits}
__device__ __align__(256) unsigned long long g_degcnt[NN]; // cnt<<32 | w*2^24
__device__ __align__(256) float g_dinv[NN];
__device__ __align__(256) int   g_cnt[NN];
__device__ __align__(256) int   g_rowstart[NN + 1];
__device__ __align__(256) int   g_cursor[NN];
__device__ __align__(256) int   g_totals[SCAN_BLOCKS];

__device__ __forceinline__ float warp_sum(float s) {
#pragma unroll
    for (int o = 16; o; o >>= 1) s += __shfl_xor_sync(0xffffffffu, s, o);
    return s;
}

// ---------------- Prologue: L0 embeddings -> g_a ----------------

__global__ void user_kernel(const float* __restrict__ uw, float* __restrict__ x) {
    int w    = (blockIdx.x * blockDim.x + threadIdx.x) >> 5;
    int lane = threadIdx.x & 31;
    if (w >= U_N) return;
    float2 v = ((const float2*)uw)[w * 32 + lane];
    float s  = warp_sum(v.x * v.x + v.y * v.y);
    float r  = 1.0f / fmaxf(sqrtf(s), 1e-12f);
    ((float2*)x)[w * 32 + lane] = make_float2(v.x * r, v.y * r);
}

__global__ void item_kernel(const float* __restrict__ audio,
                            const float* __restrict__ art,
                            const float* __restrict__ alb,
                            const float* __restrict__ W,     // [64, 128]
                            const float* __restrict__ bias,  // [64]
                            const int* __restrict__ aid,
                            const int* __restrict__ bid,
                            float* __restrict__ x) {
    __shared__ float WT[128 * 64];   // WT[k*64+d] = W[d*128+k]
    __shared__ float feat[8][128];
    int tid = threadIdx.x;
    for (int idx = tid; idx < 64 * 128; idx += 256) {
        int d = idx >> 7, k = idx & 127;
        WT[k * 64 + d] = W[idx];
    }
    __syncthreads();

    int w = tid >> 5, lane = tid & 31;
    int item = blockIdx.x * 8 + w;
    if (item < I_N) {
        int a = aid[item], bb = bid[item];
        feat[w][lane]      = audio[item * 64 + lane];
        feat[w][lane + 32] = audio[item * 64 + lane + 32];
        feat[w][64 + lane] = art[a * 64 + lane]      + alb[bb * 64 + lane];
        feat[w][96 + lane] = art[a * 64 + lane + 32] + alb[bb * 64 + lane + 32];
    }
    __syncwarp();
    if (item >= I_N) return;

    float a0 = 0.f, a1 = 0.f;
#pragma unroll
    for (int k = 0; k < 128; k++) {
        float f = feat[w][k];
        a0 = fmaf(f, WT[k * 64 + lane],      a0);
        a1 = fmaf(f, WT[k * 64 + lane + 32], a1);
    }
    a0 += bias[lane];
    a1 += bias[lane + 32];
    float s = warp_sum(a0 * a0 + a1 * a1);
    float r = 1.0f / fmaxf(sqrtf(s), 1e-12f);
    int base = (U_N + item) * 64;
    x[base + lane]      = a0 * r;
    x[base + lane + 32] = a1 * r;
}

// ---------------- Degrees + CSR build ----------------

__global__ void node_init_kernel() {
    int n = blockIdx.x * blockDim.x + threadIdx.x;
    if (n < NN) g_degcnt[n] = 0ULL;
}

// one packed 64-bit atomic per endpoint: cnt in high 32, w*2^24 fixed point low
__global__ void deg_cnt_kernel(const float* __restrict__ ew,
                               const int* __restrict__ ui,
                               const int* __restrict__ ii) {
    int e = blockIdx.x * blockDim.x + threadIdx.x;
    if (e >= E_N) return;
    float w = fmaxf(ew[e], 1e-6f);
    unsigned long long pack =
        (1ULL << 32) | (unsigned long long)__float2uint_rn(w * 16777216.0f);
    atomicAdd(&g_degcnt[ui[e]], pack);
    atomicAdd(&g_degcnt[U_N + ii[e]], pack);
}

__global__ void dinv_kernel() {
    int n = blockIdx.x * blockDim.x + threadIdx.x;
    if (n >= NN) return;
    unsigned long long p = g_degcnt[n];
    float deg = 1.0f + (float)(unsigned)(p & 0xffffffffu) * 5.9604644775390625e-8f; // /2^24
    g_dinv[n] = rsqrtf(deg);
    g_cnt[n]  = (int)(p >> 32);
}

// --- scan A: per-block (1024-elem) totals ---
__global__ void scanA_kernel() {
    int t = threadIdx.x;
    int base = blockIdx.x * SCAN_ELEMS + t * 4;
    int s = 0;
#pragma unroll
    for (int k = 0; k < 4; k++) {
        int id = base + k;
        if (id < NN) s += g_cnt[id];
    }
    __shared__ int sh[256];
    sh[t] = s; __syncthreads();
    for (int o = 128; o; o >>= 1) {
        if (t < o) sh[t] += sh[t + o];
        __syncthreads();
    }
    if (t == 0) g_totals[blockIdx.x] = sh[0];
}

// --- scan B: exclusive scan of block totals (single block) ---
__global__ void scanB_kernel() {
    __shared__ int sh[256];
    int t = threadIdx.x;
    int mine = (t < SCAN_BLOCKS) ? g_totals[t] : 0;
    sh[t] = mine; __syncthreads();
    for (int o = 1; o < 256; o <<= 1) {
        int v = (t >= o) ? sh[t - o] : 0;
        __syncthreads();
        sh[t] += v;
        __syncthreads();
    }
    if (t < SCAN_BLOCKS) g_totals[t] = sh[t] - mine;  // exclusive
    if (t == 255) g_rowstart[NN] = sh[255];           // grand total = 2E
}

// --- scan C: full exclusive positions -> rowstart + cursor ---
__global__ void scanC_kernel() {
    int t = threadIdx.x;
    int base = blockIdx.x * SCAN_ELEMS + t * 4;
    int v[4]; int s = 0;
#pragma unroll
    for (int k = 0; k < 4; k++) {
        int id = base + k;
        v[k] = (id < NN) ? g_cnt[id] : 0;
        s += v[k];
    }
    __shared__ int sh[256];
    sh[t] = s; __syncthreads();
    for (int o = 1; o < 256; o <<= 1) {
        int x = (t >= o) ? sh[t - o] : 0;
        __syncthreads();
        sh[t] += x;
        __syncthreads();
    }
    int p = g_totals[blockIdx.x] + (sh[t] - s);
#pragma unroll
    for (int k = 0; k < 4; k++) {
        int id = base + k;
        if (id < NN) { g_rowstart[id] = p; g_cursor[id] = p; }
        p += v[k];
    }
}

// --- fill adjacency: (src, coef) into both endpoints' lists ---
__global__ void fill_kernel(const float* __restrict__ ew,
                            const int* __restrict__ ui,
                            const int* __restrict__ ii) {
    int e = blockIdx.x * blockDim.x + threadIdx.x;
    if (e >= E_N) return;
    int u = ui[e], it = U_N + ii[e];
    float w = fmaxf(ew[e], 1e-6f);
    float c = g_dinv[u] * w * g_dinv[it];
    int cb = __float_as_int(c);
    int pu = atomicAdd(&g_cursor[u], 1);
    int pi = atomicAdd(&g_cursor[it], 1);
    g_entries[pu] = make_int2(it, cb);
    g_entries[pi] = make_int2(u, cb);
}

// ---------------- Propagation core ----------------
// Computes xn[row] = dinv^2 * x[row] + sum c * x[src] into (a0, a1) registers.
// Lane-parallel entry fetch + shfl broadcast: 32 independent gathers in flight.
__device__ __forceinline__ void gather_row(const float* __restrict__ x,
                                           int row, int lane,
                                           float& a0, float& a1) {
    int s   = g_rowstart[row];
    int end = g_rowstart[row + 1];
    float di = g_dinv[row];
    float c0 = di * di;
    float2 xv = ((const float2*)x)[row * 32 + lane];
    a0 = c0 * xv.x; a1 = c0 * xv.y;

    for (int base = s; base < end; base += 32) {
        int idx = base + lane;
        int2 my = (idx < end) ? __ldg(g_entries + idx) : make_int2(0, 0);
        int m = min(32, end - base);
        int j = 0;
        for (; j + 8 <= m; j += 8) {
#pragma unroll
            for (int k = 0; k < 8; k++) {
                int   sr = __shfl_sync(0xffffffffu, my.x, j + k);
                float w  = __int_as_float(__shfl_sync(0xffffffffu, my.y, j + k));
                float2 v = ((const float2*)x)[sr * 32 + lane];
                a0 = fmaf(w, v.x, a0);
                a1 = fmaf(w, v.y, a1);
            }
        }
        for (; j < m; j++) {
            int   sr = __shfl_sync(0xffffffffu, my.x, j);
            float w  = __int_as_float(__shfl_sync(0xffffffffu, my.y, j));
            float2 v = ((const float2*)x)[sr * 32 + lane];
            a0 = fmaf(w, v.x, a0);
            a1 = fmaf(w, v.y, a1);
        }
    }
}

__global__ void gather_kernel(const float* __restrict__ x, float* __restrict__ xn) {
    int row  = (blockIdx.x * blockDim.x + threadIdx.x) >> 5;
    int lane = threadIdx.x & 31;
    if (row >= NN) return;
    float a0, a1;
    gather_row(x, row, lane, a0, a1);
    ((float2*)xn)[row * 32 + lane] = make_float2(a0, a1);
}

// Layer 3 fused with epilogue: x3 = P x2; out = l2norm((x0+x1+x2+x3)/4)
__global__ void gather_final_kernel(const float* __restrict__ x2,
                                    const float* __restrict__ x0,
                                    const float* __restrict__ x1,
                                    float* __restrict__ out) {
    int row  = (blockIdx.x * blockDim.x + threadIdx.x) >> 5;
    int lane = threadIdx.x & 31;
    if (row >= NN) return;
    float a0, a1;
    gather_row(x2, row, lane, a0, a1);
    float2 v0 = ((const float2*)x0)[row * 32 + lane];
    float2 v1 = ((const float2*)x1)[row * 32 + lane];
    float2 v2 = ((const float2*)x2)[row * 32 + lane];
    float t0 = (v0.x + v1.x + v2.x + a0) * 0.25f;
    float t1 = (v0.y + v1.y + v2.y + a1) * 0.25f;
    float s  = warp_sum(t0 * t0 + t1 * t1);
    float r  = 1.0f / fmaxf(sqrtf(s), 1e-12f);
    ((float2*)out)[row * 32 + lane] = make_float2(t0 * r, t1 * r);
}

// ---------------- Launch ----------------

extern "C" void kernel_launch(void* const* d_in, const int* in_sizes, int n_in,
                              void* d_out, int out_size) {
    const float* user_w      = (const float*)d_in[0];
    const float* item_audio  = (const float*)d_in[1];
    const float* artist_w    = (const float*)d_in[2];
    const float* album_w     = (const float*)d_in[3];
    const float* proj_W      = (const float*)d_in[4];
    const float* proj_b      = (const float*)d_in[5];
    const float* edge_weight = (const float*)d_in[6];
    const int*   u_idx       = (const int*)d_in[7];
    const int*   i_idx       = (const int*)d_in[8];
    const int*   artist_ids  = (const int*)d_in[9];
    const int*   album_ids   = (const int*)d_in[10];
    float* out = (float*)d_out;

    float *pa, *pb, *pc;
    cudaGetSymbolAddress((void**)&pa, g_a);
    cudaGetSymbolAddress((void**)&pb, g_b);
    cudaGetSymbolAddress((void**)&pc, g_c);

    const int T = 256;
    const int node_blocks = (NN + T - 1) / T;
    const int edge_blocks = (E_N + T - 1) / T;
    const int row_blocks  = (NN * 32 + T - 1) / T;   // one warp per row

    // L0 embeddings -> x0 (g_a)
    user_kernel<<<(U_N * 32) / T, T>>>(user_w, pa);
    item_kernel<<<I_N / 8, T>>>(item_audio, artist_w, album_w, proj_W, proj_b,
                                artist_ids, album_ids, pa);

    // Degrees, dinv, CSR build
    node_init_kernel<<<node_blocks, T>>>();
    deg_cnt_kernel<<<edge_blocks, T>>>(edge_weight, u_idx, i_idx);
    dinv_kernel<<<node_blocks, T>>>();
    scanA_kernel<<<SCAN_BLOCKS, 256>>>();
    scanB_kernel<<<1, 256>>>();
    scanC_kernel<<<SCAN_BLOCKS, 256>>>();
    fill_kernel<<<edge_blocks, T>>>(edge_weight, u_idx, i_idx);

    // 3 LGConv layers; layer 3 fused with the epilogue
    gather_kernel<<<row_blocks, T>>>(pa, pb);          // x1
    gather_kernel<<<row_blocks, T>>>(pb, pc);          // x2
    gather_final_kernel<<<row_blocks, T>>>(pc, pa, pb, out);
}